// round 15
// baseline (speedup 1.0000x reference)
#include <cuda_runtime.h>
#include <cuda_fp16.h>

#define NVOX (128*128*128)
#define NBATCH 2
#define NTHREADS (NBATCH*NVOX)
#define INT_STEPS 7

// Max constant-offset spill past the last valid voxel: 16384+128+1 voxels.
// Tail-pad with zeros (static __device__ arrays are zero-initialized); spilled
// reads are always multiplied by an exact 0.0 weight (clip => frac == 0).
#define TAILPAD 16640

// State: half4 (z,y,x,0) packed as uint2 (8B), ping-pong. fp32 math in-register.
__device__ uint2 g_mA[NBATCH*NVOX + TAILPAD];
__device__ uint2 g_mB[NBATCH*NVOX + TAILPAD];

__device__ __forceinline__ uint2 pack_h4(float z, float y, float x) {
    __half2 a = __floats2half2_rn(z, y);
    __half2 b = __floats2half2_rn(x, 0.0f);
    uint2 m;
    m.x = *(const unsigned int*)&a;
    m.y = *(const unsigned int*)&b;
    return m;
}

__device__ __forceinline__ float3 unpack_h4(uint2 m) {
    __half2 a = *(const __half2*)&m.x;
    __half2 b = *(const __half2*)&m.y;
    float2 zy = __half22float2(a);
    return make_float3(zy.x, zy.y, __half2float(__low2half(b)));
}

// Gather load: non-coherent, L1 evict_last — corner rows are re-referenced by
// neighboring warps/row-offsets, so bias them to survive in L1.
__device__ __forceinline__ uint2 ldg_el(const uint2* p) {
    uint2 v;
    asm volatile("ld.global.nc.L1::evict_last.v2.u32 {%0, %1}, [%2];"
                 : "=r"(v.x), "=r"(v.y) : "l"(p));
    return v;
}

// Streaming (evict-first) stores: dst is never re-read within the step, so
// keep it from displacing gather-hot src lines in L1.
__device__ __forceinline__ void stcs_u2(uint2* p, uint2 v) {
    asm volatile("st.global.cs.v2.u32 [%0], {%1, %2};"
                 :: "l"(p), "r"(v.x), "r"(v.y) : "memory");
}
__device__ __forceinline__ void stcs_f(float* p, float v) {
    asm volatile("st.global.cs.f32 [%0], %1;" :: "l"(p), "f"(v) : "memory");
}

// ---------------------------------------------------------------------------
// v0 = vel/128, packed [b,z,y,x,3] -> half4 state
// ---------------------------------------------------------------------------
__global__ void __launch_bounds__(256)
scale_pack_kernel(const float* __restrict__ in, uint2* __restrict__ m) {
    int i = blockIdx.x * blockDim.x + threadIdx.x;
    const float s = 1.0f / 128.0f;
    float v0 = in[i * 3 + 0] * s;
    float v1 = in[i * 3 + 1] * s;
    float v2 = in[i * 3 + 2] * s;
    stcs_u2(m + i, pack_h4(v0, v1, v2));
}

// ---------------------------------------------------------------------------
// Trilinear over 8 corners at compile-time constant offsets; one LDG.64 per
// corner fetches all 3 channels.
// ---------------------------------------------------------------------------
__device__ __forceinline__ float3 gather_lerp(const uint2* __restrict__ g,
                                              float wx, float wy, float wz) {
    float3 c000 = unpack_h4(ldg_el(g + 0));
    float3 c001 = unpack_h4(ldg_el(g + 1));
    float3 c010 = unpack_h4(ldg_el(g + 128));
    float3 c011 = unpack_h4(ldg_el(g + 129));
    float3 c100 = unpack_h4(ldg_el(g + 16384));
    float3 c101 = unpack_h4(ldg_el(g + 16385));
    float3 c110 = unpack_h4(ldg_el(g + 16512));
    float3 c111 = unpack_h4(ldg_el(g + 16513));

    float a00x = fmaf(wx, c001.x - c000.x, c000.x);
    float a00y = fmaf(wx, c001.y - c000.y, c000.y);
    float a00z = fmaf(wx, c001.z - c000.z, c000.z);
    float a01x = fmaf(wx, c011.x - c010.x, c010.x);
    float a01y = fmaf(wx, c011.y - c010.y, c010.y);
    float a01z = fmaf(wx, c011.z - c010.z, c010.z);
    float a10x = fmaf(wx, c101.x - c100.x, c100.x);
    float a10y = fmaf(wx, c101.y - c100.y, c100.y);
    float a10z = fmaf(wx, c101.z - c100.z, c100.z);
    float a11x = fmaf(wx, c111.x - c110.x, c110.x);
    float a11y = fmaf(wx, c111.y - c110.y, c110.y);
    float a11z = fmaf(wx, c111.z - c110.z, c110.z);

    float b0x = fmaf(wy, a01x - a00x, a00x);
    float b0y = fmaf(wy, a01y - a00y, a00y);
    float b0z = fmaf(wy, a01z - a00z, a00z);
    float b1x = fmaf(wy, a11x - a10x, a10x);
    float b1y = fmaf(wy, a11y - a10y, a10y);
    float b1z = fmaf(wy, a11z - a10z, a10z);

    return make_float3(fmaf(wz, b1x - b0x, b0x),
                       fmaf(wz, b1y - b0y, b0y),
                       fmaf(wz, b1z - b0z, b0z));
}

// ---------------------------------------------------------------------------
// One step: v <- v + trilerp(v, grid + v), state entirely in half4.
// ---------------------------------------------------------------------------
template<bool FINAL>
__global__ void __launch_bounds__(256)
step_kernel(const uint2* __restrict__ msrc, uint2* __restrict__ mdst,
            float* __restrict__ out) {
    int idx = blockIdx.x * blockDim.x + threadIdx.x;   // 0..NTHREADS-1
    int x = idx & 127;
    int y = (idx >> 7) & 127;
    int z = (idx >> 14) & 127;
    int b = idx >> 21;
    int vox = idx & (NVOX - 1);

    const uint2* mb = msrc + b * NVOX;
    float3 v = unpack_h4(__ldg(mb + vox));

    float lz = fminf(fmaxf((float)z + v.x, 0.0f), 127.0f);
    float ly = fminf(fmaxf((float)y + v.y, 0.0f), 127.0f);
    float lx = fminf(fmaxf((float)x + v.z, 0.0f), 127.0f);

    int iz = __float2int_rd(lz);
    int iy = __float2int_rd(ly);
    int ix = __float2int_rd(lx);
    float wz = lz - (float)iz;
    float wy = ly - (float)iy;
    float wx = lx - (float)ix;
    // i1 clamp elided: when i0 == 127 the weight is exactly 0 and the
    // +1/+128/+16384 spill reads finite in-buffer or zero-pad data.
    int o000 = (((iz << 7) + iy) << 7) + ix;

    float3 r = gather_lerp(mb + o000, wx, wy, wz);

    float resz = v.x + r.x;
    float resy = v.y + r.y;
    float resx = v.z + r.z;

    if (FINAL) {
        float* o = out + (size_t)idx * 3;
        stcs_f(o + 0, resz);
        stcs_f(o + 1, resy);
        stcs_f(o + 2, resx);
    } else {
        stcs_u2(mdst + b * NVOX + vox, pack_h4(resz, resy, resx));
    }
}

// ---------------------------------------------------------------------------
extern "C" void kernel_launch(void* const* d_in, const int* in_sizes, int n_in,
                              void* d_out, int out_size) {
    const float* vel = (const float*)d_in[0];
    float* out = (float*)d_out;

    uint2 *mA, *mB;
    cudaGetSymbolAddress((void**)&mA, g_mA);
    cudaGetSymbolAddress((void**)&mB, g_mB);

    const int nblocks = NTHREADS / 256;

    scale_pack_kernel<<<nblocks, 256>>>(vel, mA);

    const uint2* ms = mA;
    uint2* md = mB;
    for (int s = 0; s < INT_STEPS - 1; s++) {
        step_kernel<false><<<nblocks, 256>>>(ms, md, nullptr);
        const uint2* t = md;
        md = (uint2*)ms;
        ms = t;
    }
    step_kernel<true><<<nblocks, 256>>>(ms, nullptr, out);
}

// round 16
// speedup vs baseline: 1.0066x; 1.0066x over previous
#include <cuda_runtime.h>
#include <cuda_fp16.h>

#define NVOX (128*128*128)
#define NBATCH 2
#define NTHREADS (NBATCH*NVOX)
#define INT_STEPS 7
#define BLOCK 384

#define TAILPAD 16640

__device__ uint2 g_mA[NBATCH*NVOX + TAILPAD];
__device__ uint2 g_mB[NBATCH*NVOX + TAILPAD];

__device__ __forceinline__ uint2 pack_h4(float z, float y, float x) {
    __half2 a = __floats2half2_rn(z, y);
    __half2 b = __floats2half2_rn(x, 0.0f);
    uint2 m;
    m.x = *(const unsigned int*)&a;
    m.y = *(const unsigned int*)&b;
    return m;
}

__device__ __forceinline__ float3 unpack_h4(uint2 m) {
    __half2 a = *(const __half2*)&m.x;
    __half2 b = *(const __half2*)&m.y;
    float2 zy = __half22float2(a);
    return make_float3(zy.x, zy.y, __half2float(__low2half(b)));
}

__device__ __forceinline__ void stcs_u2(uint2* p, uint2 v) {
    asm volatile("st.global.cs.v2.u32 [%0], {%1, %2};"
                 :: "l"(p), "r"(v.x), "r"(v.y) : "memory");
}
__device__ __forceinline__ void stcs_f(float* p, float v) {
    asm volatile("st.global.cs.f32 [%0], %1;" :: "l"(p), "f"(v) : "memory");
}

__global__ void __launch_bounds__(256)
scale_pack_kernel(const float* __restrict__ in, uint2* __restrict__ m) {
    int i = blockIdx.x * blockDim.x + threadIdx.x;
    const float s = 1.0f / 128.0f;
    float v0 = in[i * 3 + 0] * s;
    float v1 = in[i * 3 + 1] * s;
    float v2 = in[i * 3 + 2] * s;
    stcs_u2(m + i, pack_h4(v0, v1, v2));
}

__device__ __forceinline__ float3 gather_lerp(const uint2* __restrict__ g,
                                              float wx, float wy, float wz) {
    float3 c000 = unpack_h4(__ldg(g + 0));
    float3 c001 = unpack_h4(__ldg(g + 1));
    float3 c010 = unpack_h4(__ldg(g + 128));
    float3 c011 = unpack_h4(__ldg(g + 129));
    float3 c100 = unpack_h4(__ldg(g + 16384));
    float3 c101 = unpack_h4(__ldg(g + 16385));
    float3 c110 = unpack_h4(__ldg(g + 16512));
    float3 c111 = unpack_h4(__ldg(g + 16513));

    float a00x = fmaf(wx, c001.x - c000.x, c000.x);
    float a00y = fmaf(wx, c001.y - c000.y, c000.y);
    float a00z = fmaf(wx, c001.z - c000.z, c000.z);
    float a01x = fmaf(wx, c011.x - c010.x, c010.x);
    float a01y = fmaf(wx, c011.y - c010.y, c010.y);
    float a01z = fmaf(wx, c011.z - c010.z, c010.z);
    float a10x = fmaf(wx, c101.x - c100.x, c100.x);
    float a10y = fmaf(wx, c101.y - c100.y, c100.y);
    float a10z = fmaf(wx, c101.z - c100.z, c100.z);
    float a11x = fmaf(wx, c111.x - c110.x, c110.x);
    float a11y = fmaf(wx, c111.y - c110.y, c110.y);
    float a11z = fmaf(wx, c111.z - c110.z, c110.z);

    float b0x = fmaf(wy, a01x - a00x, a00x);
    float b0y = fmaf(wy, a01y - a00y, a00y);
    float b0z = fmaf(wy, a01z - a00z, a00z);
    float b1x = fmaf(wy, a11x - a10x, a10x);
    float b1y = fmaf(wy, a11y - a10y, a10y);
    float b1z = fmaf(wy, a11z - a10z, a10z);

    return make_float3(fmaf(wz, b1x - b0x, b0x),
                       fmaf(wz, b1y - b0y, b0y),
                       fmaf(wz, b1z - b0z, b0z));
}

template<bool FINAL>
__global__ void __launch_bounds__(BLOCK)
step_kernel(const uint2* __restrict__ msrc, uint2* __restrict__ mdst,
            float* __restrict__ out) {
    int idx = blockIdx.x * blockDim.x + threadIdx.x;
    if (idx >= NTHREADS) return;
    int x = idx & 127;
    int y = (idx >> 7) & 127;
    int z = (idx >> 14) & 127;
    int b = idx >> 21;
    int vox = idx & (NVOX - 1);

    const uint2* mb = msrc + b * NVOX;
    float3 v = unpack_h4(__ldg(mb + vox));

    float lz = fminf(fmaxf((float)z + v.x, 0.0f), 127.0f);
    float ly = fminf(fmaxf((float)y + v.y, 0.0f), 127.0f);
    float lx = fminf(fmaxf((float)x + v.z, 0.0f), 127.0f);

    int iz = __float2int_rd(lz);
    int iy = __float2int_rd(ly);
    int ix = __float2int_rd(lx);
    float wz = lz - (float)iz;
    float wy = ly - (float)iy;
    float wx = lx - (float)ix;
    int o000 = (((iz << 7) + iy) << 7) + ix;

    float3 r = gather_lerp(mb + o000, wx, wy, wz);

    float resz = v.x + r.x;
    float resy = v.y + r.y;
    float resx = v.z + r.z;

    if (FINAL) {
        float* o = out + (size_t)idx * 3;
        stcs_f(o + 0, resz);
        stcs_f(o + 1, resy);
        stcs_f(o + 2, resx);
    } else {
        stcs_u2(mdst + b * NVOX + vox, pack_h4(resz, resy, resx));
    }
}

extern "C" void kernel_launch(void* const* d_in, const int* in_sizes, int n_in,
                              void* d_out, int out_size) {
    const float* vel = (const float*)d_in[0];
    float* out = (float*)d_out;

    uint2 *mA, *mB;
    cudaGetSymbolAddress((void**)&mA, g_mA);
    cudaGetSymbolAddress((void**)&mB, g_mB);

    scale_pack_kernel<<<NTHREADS / 256, 256>>>(vel, mA);

    const int nb = (NTHREADS + BLOCK - 1) / BLOCK;
    const uint2* ms = mA;
    uint2* md = mB;
    for (int s = 0; s < INT_STEPS - 1; s++) {
        step_kernel<false><<<nb, BLOCK>>>(ms, md, nullptr);
        const uint2* t = md;
        md = (uint2*)ms;
        ms = t;
    }
    step_kernel<true><<<nb, BLOCK>>>(ms, nullptr, out);
}